// round 11
// baseline (speedup 1.0000x reference)
#include <cuda_runtime.h>
#include <cstdint>

#define DIMC 2048
#define NH 16
#define HD 128
#define BATCH 4
#define SEQT 2048

// Scratch (device globals: allocation-free scratch per harness rules)
__device__ float g_k[(size_t)BATCH * NH * SEQT * HD];
__device__ float g_v[(size_t)BATCH * NH * SEQT * HD];
__device__ float g_q[(size_t)BATCH * NH * SEQT * HD];
__device__ float g_att[(size_t)BATCH * SEQT * DIMC];

__device__ __forceinline__ float tf32r(float x) {
    uint32_t u;
    asm("cvt.rna.tf32.f32 %0, %1;" : "=r"(u) : "f"(x));
    return __uint_as_float(u);
}

__device__ __forceinline__ void mma_tf32(float* c, const uint32_t* a, const uint32_t* b) {
    asm volatile(
        "mma.sync.aligned.m16n8k8.row.col.f32.tf32.tf32.f32 "
        "{%0,%1,%2,%3}, {%4,%5,%6,%7}, {%8,%9}, {%0,%1,%2,%3};"
        : "+f"(c[0]), "+f"(c[1]), "+f"(c[2]), "+f"(c[3])
        : "r"(a[0]), "r"(a[1]), "r"(a[2]), "r"(a[3]), "r"(b[0]), "r"(b[1]));
}

// k-permutation within a 32-k chunk: thread t's k's {t,t+4,...,t+28} contiguous.
// pos(k) = (k&3)*8 + ((k>>2)&7)   (+32 per 32-chunk)

// ============================================================================
// tf32 GEMM: C[M,N] = A[M,K] @ W[K,N] + bias
// BM=128, BN=128, BK=32, 256 threads (8 warps: 4 along M x 2 along N).
// Smem: As[m][kperm] (stride 36), Bs transposed [n][kperm] (stride 36).
// Fragment loads are LDS.128, conflict-free.
// ============================================================================
template <int MODE>
__global__ void __launch_bounds__(256, 2) gemm_tf32(
    const float* __restrict__ A, const float* __restrict__ W,
    const float* __restrict__ bias, float* __restrict__ Cout,
    int M, int N, int K)
{
    __shared__ float As[128 * 36];
    __shared__ float Bs[128 * 36];

    const int tid = threadIdx.x;
    const int warp = tid >> 5, lane = tid & 31;
    const int g = lane >> 2, t = lane & 3;
    const int wm = warp >> 1, wn = warp & 1;
    const int mBase = blockIdx.y * 128;
    const int nBase = blockIdx.x * 128;

    float acc[2][8][4] = {};

    for (int k0 = 0; k0 < K; k0 += 32) {
        // ---- Fill As[m*36 + pos(k)]: thread float4 along k, scatter 4 STS.
        // Lane map: m-offset = lane&7, j-offset = lane>>3 (conflict-free STS).
        #pragma unroll
        for (int i = 0; i < 4; i++) {
            int f = tid + (i << 8);
            int m = (f & 7) | (((f >> 5) & 15) << 3);
            int j = ((f >> 3) & 3) | (((f >> 9) & 1) << 2);
            float4 v = *(const float4*)(A + (size_t)(mBase + m) * K + k0 + 4 * j);
            float* dst = &As[m * 36 + (j & 7)];
            dst[0]  = tf32r(v.x);
            dst[8]  = tf32r(v.y);
            dst[16] = tf32r(v.z);
            dst[24] = tf32r(v.w);
        }
        // ---- Fill Bs transposed: Bs[n*36 + pos(k)]: thread float4 along n,
        // scatter to 4 rows. Lane map: k-low4 = lane&15, n4-bit = lane>>4.
        #pragma unroll
        for (int i = 0; i < 4; i++) {
            int f = tid + (i << 8);
            int k = (f & 15) | (((f >> 8) & 1) << 4);
            int n4 = ((f >> 4) & 1) | (((f >> 5) & 7) << 1) | (((f >> 9) & 1) << 4);
            float4 v = *(const float4*)(W + (size_t)(k0 + k) * N + nBase + 4 * n4);
            float* dst = &Bs[(4 * n4) * 36 + (k & 3) * 8 + ((k >> 2) & 7)];
            dst[0]   = tf32r(v.x);
            dst[36]  = tf32r(v.y);
            dst[72]  = tf32r(v.z);
            dst[108] = tf32r(v.w);
        }
        __syncthreads();

        // ---- Compute: 2 k-pairs, vectorized fragment loads (LDS.128)
        #pragma unroll
        for (int pr = 0; pr < 2; pr++) {
            float4 av[2][2];
            #pragma unroll
            for (int mt = 0; mt < 2; mt++)
                #pragma unroll
                for (int r = 0; r < 2; r++)
                    av[mt][r] = *(const float4*)&As[(wm * 32 + mt * 16 + g + 8 * r) * 36 + t * 8 + 4 * pr];
            float4 bv[8];
            #pragma unroll
            for (int nt = 0; nt < 8; nt++)
                bv[nt] = *(const float4*)&Bs[(wn * 64 + nt * 8 + g) * 36 + t * 8 + 4 * pr];

            #pragma unroll
            for (int s2 = 0; s2 < 2; s2++) {
                #pragma unroll
                for (int mt = 0; mt < 2; mt++) {
                    uint32_t a[4];
                    a[0] = __float_as_uint(((const float*)&av[mt][0])[2 * s2]);
                    a[1] = __float_as_uint(((const float*)&av[mt][1])[2 * s2]);
                    a[2] = __float_as_uint(((const float*)&av[mt][0])[2 * s2 + 1]);
                    a[3] = __float_as_uint(((const float*)&av[mt][1])[2 * s2 + 1]);
                    #pragma unroll
                    for (int nt = 0; nt < 8; nt++) {
                        uint32_t b[2];
                        b[0] = __float_as_uint(((const float*)&bv[nt])[2 * s2]);
                        b[1] = __float_as_uint(((const float*)&bv[nt])[2 * s2 + 1]);
                        mma_tf32(acc[mt][nt], a, b);
                    }
                }
            }
        }
        __syncthreads();
    }

    // Epilogue
    #pragma unroll
    for (int mt = 0; mt < 2; mt++) {
        #pragma unroll
        for (int nt = 0; nt < 8; nt++) {
            #pragma unroll
            for (int e = 0; e < 4; e++) {
                const int r = mBase + wm * 32 + mt * 16 + g + (e >> 1) * 8;
                const int c = nBase + wn * 64 + nt * 8 + t * 2 + (e & 1);
                float val = acc[mt][nt][e] + bias[c];
                if (MODE == 0) {
                    Cout[(size_t)r * N + c] = val;
                } else if (MODE == 1) {
                    const int b_ = r >> 11, tt = r & 2047;
                    const int cc = c & 2047;
                    const int h = cc >> 7, d = cc & 127;
                    float* dst = (c < 2048) ? g_k : g_v;
                    dst[(((size_t)(b_ * NH + h)) * SEQT + tt) * HD + d] = val;
                } else {
                    const int b_ = r >> 11, tt = r & 2047;
                    const int h = c >> 7, d = c & 127;
                    g_q[(((size_t)(b_ * NH + h)) * SEQT + tt) * HD + d] = val;
                }
            }
        }
    }
}

// ============================================================================
// Flash attention (causal), tf32 mma, vectorized fragments.
// Smem: Qs[128][dperm,132], Ks[64][dperm,132], Vn[128 d][keyperm,68],
//       Ps[128][keyperm,68]. All fragment loads LDS.128.
// ============================================================================
__global__ void __launch_bounds__(256, 1) attn_kernel()
{
    extern __shared__ float sm[];
    float* Qs = sm;                    // 128*132
    float* Ks = Qs + 128 * 132;        // 64*132
    float* Vn = Ks + 64 * 132;         // 128*68 (transposed: row=d, col=keyperm)
    float* Ps = Vn + 128 * 68;         // 128*68

    const int bh = blockIdx.y;
    const int qt = blockIdx.x;
    const int qBase = qt * 128;
    const int tid = threadIdx.x, warp = tid >> 5, lane = tid & 31;
    const int g = lane >> 2, t = lane & 3;
    const int rowW = warp * 16;
    const float scale = 0.08838834764831845f;  // 1/sqrt(128)

    const float* Qg = g_q + (size_t)bh * SEQT * HD;
    const float* Kg = g_k + (size_t)bh * SEQT * HD;
    const float* Vg = g_v + (size_t)bh * SEQT * HD;

    // ---- Load Q tile, pre-scaled, permuted layout Qs[m*132 + 32*(j>>3) + (d&3)*8 + (j&7)]
    // thread float4 along d (j = d>>2). Lane map: m-off = lane&7, j-off = lane>>3.
    #pragma unroll
    for (int i = 0; i < 16; i++) {
        int f = tid + (i << 8);
        int m = (f & 7) | (((f >> 5) & 15) << 3);
        int j = ((f >> 3) & 3) | (((f >> 9) & 7) << 2);
        float4 v = *(const float4*)(Qg + (size_t)(qBase + m) * HD + 4 * j);
        float* dst = &Qs[m * 132 + ((j >> 3) << 5) + (j & 7)];
        dst[0]  = tf32r(v.x * scale);
        dst[8]  = tf32r(v.y * scale);
        dst[16] = tf32r(v.z * scale);
        dst[24] = tf32r(v.w * scale);
    }

    float o[16][4] = {};
    float m_[2], l_[2];
    m_[0] = m_[1] = -1e30f;
    l_[0] = l_[1] = 0.0f;

    const int nkt = 2 * qt + 2;
    for (int kt = 0; kt < nkt; kt++) {
        const int kBase = kt * 64;

        // ---- K tile [64 key][128 d] -> Ks[key*132 + dperm]
        #pragma unroll
        for (int i = 0; i < 8; i++) {
            int f = tid + (i << 8);
            int key = (f & 7) | (((f >> 5) & 7) << 3);
            int j = ((f >> 3) & 3) | (((f >> 8) & 7) << 2);
            float4 v = *(const float4*)(Kg + (size_t)(kBase + key) * HD + 4 * j);
            float* dst = &Ks[key * 132 + ((j >> 3) << 5) + (j & 7)];
            dst[0]  = tf32r(v.x);
            dst[8]  = tf32r(v.y);
            dst[16] = tf32r(v.z);
            dst[24] = tf32r(v.w);
        }
        // ---- V tile [64 key][128 d] -> transposed Vn[d*68 + keyperm]
        // Lane map: key-low4 = lane&15, j-bit = lane>>4 (32B/row gmem reads).
        #pragma unroll
        for (int i = 0; i < 8; i++) {
            int f = tid + (i << 8);
            int key = (f & 15) | (((f >> 9) & 3) << 4);
            int j = ((f >> 4) & 1) | (((f >> 5) & 15) << 1);
            float4 v = *(const float4*)(Vg + (size_t)(kBase + key) * HD + 4 * j);
            int pos = (key & 3) * 8 + ((key >> 2) & 7) + ((key >> 5) << 5);
            float* dst = &Vn[(4 * j) * 68 + pos];
            dst[0]       = tf32r(v.x);
            dst[68]      = tf32r(v.y);
            dst[136]     = tf32r(v.z);
            dst[204]     = tf32r(v.w);
        }
        __syncthreads();

        // ---- S = Q @ K^T (warp: 16 rows x 64 keys), vectorized
        float s[8][4] = {};
        #pragma unroll
        for (int kc = 0; kc < 4; kc++) {
            #pragma unroll
            for (int pr = 0; pr < 2; pr++) {
                float4 qv[2];
                qv[0] = *(const float4*)&Qs[(rowW + g) * 132 + kc * 32 + t * 8 + 4 * pr];
                qv[1] = *(const float4*)&Qs[(rowW + g + 8) * 132 + kc * 32 + t * 8 + 4 * pr];
                float4 kv[8];
                #pragma unroll
                for (int nt = 0; nt < 8; nt++)
                    kv[nt] = *(const float4*)&Ks[(nt * 8 + g) * 132 + kc * 32 + t * 8 + 4 * pr];
                #pragma unroll
                for (int s2 = 0; s2 < 2; s2++) {
                    uint32_t a[4];
                    a[0] = __float_as_uint(((const float*)&qv[0])[2 * s2]);
                    a[1] = __float_as_uint(((const float*)&qv[1])[2 * s2]);
                    a[2] = __float_as_uint(((const float*)&qv[0])[2 * s2 + 1]);
                    a[3] = __float_as_uint(((const float*)&qv[1])[2 * s2 + 1]);
                    #pragma unroll
                    for (int nt = 0; nt < 8; nt++) {
                        uint32_t b[2];
                        b[0] = __float_as_uint(((const float*)&kv[nt])[2 * s2]);
                        b[1] = __float_as_uint(((const float*)&kv[nt])[2 * s2 + 1]);
                        mma_tf32(s[nt], a, b);
                    }
                }
            }
        }

        // Causal mask for diagonal tiles
        if (kt >= 2 * qt) {
            #pragma unroll
            for (int nt = 0; nt < 8; nt++)
                #pragma unroll
                for (int e = 0; e < 4; e++) {
                    const int key = kBase + nt * 8 + t * 2 + (e & 1);
                    const int qr = qBase + rowW + g + (e >> 1) * 8;
                    if (key > qr) s[nt][e] = -1e30f;
                }
        }

        // Online softmax (per thread: rows g and g+8)
        float mnew[2];
        #pragma unroll
        for (int rr = 0; rr < 2; rr++) {
            float mx = -1e30f;
            #pragma unroll
            for (int nt = 0; nt < 8; nt++)
                mx = fmaxf(mx, fmaxf(s[nt][rr * 2], s[nt][rr * 2 + 1]));
            mx = fmaxf(mx, __shfl_xor_sync(0xffffffffu, mx, 1));
            mx = fmaxf(mx, __shfl_xor_sync(0xffffffffu, mx, 2));
            mnew[rr] = fmaxf(m_[rr], mx);
        }
        float corr[2];
        corr[0] = __expf(m_[0] - mnew[0]);
        corr[1] = __expf(m_[1] - mnew[1]);

        float rs[2] = {0.0f, 0.0f};
        #pragma unroll
        for (int nt = 0; nt < 8; nt++)
            #pragma unroll
            for (int e = 0; e < 4; e++) {
                const int rr = e >> 1;
                float p = __expf(s[nt][e] - mnew[rr]);
                s[nt][e] = p;
                rs[rr] += p;
            }
        #pragma unroll
        for (int rr = 0; rr < 2; rr++) {
            float v = rs[rr];
            v += __shfl_xor_sync(0xffffffffu, v, 1);
            v += __shfl_xor_sync(0xffffffffu, v, 2);
            l_[rr] = l_[rr] * corr[rr] + v;
            m_[rr] = mnew[rr];
        }

        // Rescale O accumulators
        #pragma unroll
        for (int nt = 0; nt < 16; nt++)
            #pragma unroll
            for (int e = 0; e < 4; e++)
                o[nt][e] *= corr[e >> 1];

        // ---- P -> smem in key-permuted layout (pos, pos+8 for the column pair)
        #pragma unroll
        for (int nt = 0; nt < 8; nt++) {
            const int key = nt * 8 + t * 2;
            const int pos = (key & 3) * 8 + ((key >> 2) & 7) + ((key >> 5) << 5);
            Ps[(rowW + g) * 68 + pos]         = tf32r(s[nt][0]);
            Ps[(rowW + g) * 68 + pos + 8]     = tf32r(s[nt][1]);
            Ps[(rowW + g + 8) * 68 + pos]     = tf32r(s[nt][2]);
            Ps[(rowW + g + 8) * 68 + pos + 8] = tf32r(s[nt][3]);
        }
        __syncwarp();

        // ---- O += P @ V (k = 64 keys, n = 128 dims), vectorized
        #pragma unroll
        for (int kc = 0; kc < 2; kc++) {
            #pragma unroll
            for (int pr = 0; pr < 2; pr++) {
                float4 pv[2];
                pv[0] = *(const float4*)&Ps[(rowW + g) * 68 + kc * 32 + t * 8 + 4 * pr];
                pv[1] = *(const float4*)&Ps[(rowW + g + 8) * 68 + kc * 32 + t * 8 + 4 * pr];
                #pragma unroll
                for (int h = 0; h < 2; h++) {
                    float4 vv[8];
                    #pragma unroll
                    for (int nt = 0; nt < 8; nt++)
                        vv[nt] = *(const float4*)&Vn[((h * 8 + nt) * 8 + g) * 68 + kc * 32 + t * 8 + 4 * pr];
                    #pragma unroll
                    for (int s2 = 0; s2 < 2; s2++) {
                        uint32_t a[4];
                        a[0] = __float_as_uint(((const float*)&pv[0])[2 * s2]);
                        a[1] = __float_as_uint(((const float*)&pv[1])[2 * s2]);
                        a[2] = __float_as_uint(((const float*)&pv[0])[2 * s2 + 1]);
                        a[3] = __float_as_uint(((const float*)&pv[1])[2 * s2 + 1]);
                        #pragma unroll
                        for (int nt = 0; nt < 8; nt++) {
                            uint32_t b[2];
                            b[0] = __float_as_uint(((const float*)&vv[nt])[2 * s2]);
                            b[1] = __float_as_uint(((const float*)&vv[nt])[2 * s2 + 1]);
                            mma_tf32(o[h * 8 + nt], a, b);
                        }
                    }
                }
            }
        }
        __syncthreads();
    }

    // Write normalized output to g_att[b, row, h*128 + d]
    const int b_ = bh >> 4, h = bh & 15;
    const float inv0 = 1.0f / l_[0], inv1 = 1.0f / l_[1];
    #pragma unroll
    for (int nt = 0; nt < 16; nt++)
        #pragma unroll
        for (int e = 0; e < 4; e++) {
            const int rr = e >> 1;
            const int row = qBase + rowW + g + rr * 8;
            const int d = nt * 8 + t * 2 + (e & 1);
            g_att[((size_t)b_ * SEQT + row) * DIMC + h * HD + d] =
                o[nt][e] * (rr ? inv1 : inv0);
        }
}

extern "C" void kernel_launch(void* const* d_in, const int* in_sizes, int n_in,
                              void* d_out, int out_size)
{
    const float* enc = (const float*)d_in[0];
    const float* dec = (const float*)d_in[1];
    const float* Wkv = (const float*)d_in[2];
    const float* bkv = (const float*)d_in[3];
    const float* Wq  = (const float*)d_in[4];
    const float* bq  = (const float*)d_in[5];
    const float* Wo  = (const float*)d_in[6];
    const float* bo  = (const float*)d_in[7];
    float* out = (float*)d_out;

    void* attPtr = nullptr;
    cudaGetSymbolAddress(&attPtr, g_att);

    const int M = BATCH * SEQT;  // 8192
    dim3 blk(256);

    // 1) KV projection -> g_k, g_v (head-major)
    gemm_tf32<1><<<dim3((2 * DIMC) / 128, M / 128), blk>>>(
        enc, Wkv, bkv, nullptr, M, 2 * DIMC, DIMC);
    // 2) Q projection -> g_q (head-major)
    gemm_tf32<2><<<dim3(DIMC / 128, M / 128), blk>>>(
        dec, Wq, bq, nullptr, M, DIMC, DIMC);

    // 3) Causal flash attention -> g_att
    const size_t ATT_SMEM = (size_t)(128 * 132 + 64 * 132 + 128 * 68 + 128 * 68) * sizeof(float);
    cudaFuncSetAttribute((const void*)attn_kernel,
                         cudaFuncAttributeMaxDynamicSharedMemorySize, (int)ATT_SMEM);
    attn_kernel<<<dim3(SEQT / 128, BATCH * NH), blk, ATT_SMEM>>>();

    // 4) Output projection -> d_out
    gemm_tf32<0><<<dim3(DIMC / 128, M / 128), blk>>>(
        (const float*)attPtr, Wo, bo, out, M, DIMC, DIMC);
}

// round 16
// speedup vs baseline: 1.2546x; 1.2546x over previous
#include <cuda_runtime.h>
#include <cstdint>

#define DIMC 2048
#define NH 16
#define HD 128
#define BATCH 4
#define SEQT 2048

// Scratch (device globals: allocation-free scratch per harness rules)
__device__ float g_k[(size_t)BATCH * NH * SEQT * HD];
__device__ float g_v[(size_t)BATCH * NH * SEQT * HD];
__device__ float g_q[(size_t)BATCH * NH * SEQT * HD];
__device__ float g_att[(size_t)BATCH * SEQT * DIMC];
// tf32-rounded input copies (A operands for cp.async path)
__device__ float g_encr[(size_t)BATCH * SEQT * DIMC];
__device__ float g_decr[(size_t)BATCH * SEQT * DIMC];
// Transposed+tf32-rounded weights: Wkv^T (4096x2048) | Wq^T | Wo^T
__device__ float g_wt[(size_t)4 * DIMC * DIMC];

__device__ __forceinline__ float tf32r(float x) {
    uint32_t u;
    asm("cvt.rna.tf32.f32 %0, %1;" : "=r"(u) : "f"(x));
    return __uint_as_float(u);
}

__device__ __forceinline__ uint32_t smem_u32(const void* p) {
    uint32_t a;
    asm("{ .reg .u64 t; cvta.to.shared.u64 t, %1; cvt.u32.u64 %0, t; }" : "=r"(a) : "l"(p));
    return a;
}

#define CP16(dst, src) \
    asm volatile("cp.async.ca.shared.global [%0], [%1], 16;" :: "r"(dst), "l"(src) : "memory")

__device__ __forceinline__ void mma_tf32(float* c, const uint32_t* a, const uint32_t* b) {
    asm volatile(
        "mma.sync.aligned.m16n8k8.row.col.f32.tf32.tf32.f32 "
        "{%0,%1,%2,%3}, {%4,%5,%6,%7}, {%8,%9}, {%0,%1,%2,%3};"
        : "+f"(c[0]), "+f"(c[1]), "+f"(c[2]), "+f"(c[3])
        : "r"(a[0]), "r"(a[1]), "r"(a[2]), "r"(a[3]), "r"(b[0]), "r"(b[1]));
}

// ============================================================================
// tf32-round copy: dst[i] = tf32(src[i])
// ============================================================================
__global__ void round_copy(const float* __restrict__ src, float* __restrict__ dst) {
    const size_t i = ((size_t)blockIdx.x * blockDim.x + threadIdx.x) * 4;
    float4 v = *(const float4*)(src + i);
    v.x = tf32r(v.x); v.y = tf32r(v.y); v.z = tf32r(v.z); v.w = tf32r(v.w);
    *(float4*)(dst + i) = v;
}

// ============================================================================
// Weight transpose + tf32 rounding: WT[n*K + k] = tf32(W[k*N + n])
// ============================================================================
__global__ void transpose_round(const float* __restrict__ W, float* __restrict__ WT,
                                int K, int N)
{
    __shared__ float t[32][33];
    const int n0 = blockIdx.x * 32, k0 = blockIdx.y * 32;
    const int x = threadIdx.x, y = threadIdx.y;
    #pragma unroll
    for (int i = 0; i < 32; i += 8)
        t[y + i][x] = W[(size_t)(k0 + y + i) * N + n0 + x];
    __syncthreads();
    #pragma unroll
    for (int i = 0; i < 32; i += 8)
        WT[(size_t)(n0 + y + i) * K + k0 + x] = tf32r(t[x][y + i]);
}

// ============================================================================
// tf32 GEMM, cp.async double-buffered: C[M,N] = A[M,K] @ WT[N,K]^T + bias
// BM=128, BN=128, BK=32; 128 threads = 4 warps (2x2), warp tile 64x64.
// A and WT must be pre-rounded to tf32 in gmem.
// MODE 0: plain write, MODE 1: KV scatter, MODE 2: Q scatter.
// ============================================================================
#define TS (128 * 36)  // floats per stage per operand

template <int MODE>
__global__ void __launch_bounds__(128) gemm_ca(
    const float* __restrict__ A, const float* __restrict__ WT,
    const float* __restrict__ bias, float* __restrict__ Cout,
    int M, int N, int K)
{
    extern __shared__ float sm[];
    float* AsBuf = sm;            // [2][TS]
    float* BsBuf = sm + 2 * TS;   // [2][TS]

    const int tid = threadIdx.x, warp = tid >> 5, lane = tid & 31;
    const int g = lane >> 2, t = lane & 3;
    const int wm = warp >> 1, wn = warp & 1;
    const int mBase = blockIdx.y * 128, nBase = blockIdx.x * 128;

    const uint32_t sA = smem_u32(AsBuf), sB = smem_u32(BsBuf);

    float acc[4][8][4] = {};

    const int KIT = K >> 5;

    // ---- prologue: issue tile 0
    {
        const uint32_t dA = sA, dB = sB;
        #pragma unroll
        for (int u = 0; u < 8; u++) {
            const int f = tid + (u << 7);
            const int m = f >> 3, j = f & 7;
            CP16(dA + (uint32_t)(m * 36 + j * 4) * 4, A + (size_t)(mBase + m) * K + 4 * j);
            CP16(dB + (uint32_t)(m * 36 + j * 4) * 4, WT + (size_t)(nBase + m) * K + 4 * j);
        }
        asm volatile("cp.async.commit_group;" ::: "memory");
    }

    for (int i = 0; i < KIT; i++) {
        if (i + 1 < KIT) {
            const int p = (i + 1) & 1;
            const int k0 = (i + 1) << 5;
            const uint32_t dA = sA + (uint32_t)p * TS * 4;
            const uint32_t dB = sB + (uint32_t)p * TS * 4;
            #pragma unroll
            for (int u = 0; u < 8; u++) {
                const int f = tid + (u << 7);
                const int m = f >> 3, j = f & 7;
                CP16(dA + (uint32_t)(m * 36 + j * 4) * 4,
                     A + (size_t)(mBase + m) * K + k0 + 4 * j);
                CP16(dB + (uint32_t)(m * 36 + j * 4) * 4,
                     WT + (size_t)(nBase + m) * K + k0 + 4 * j);
            }
            asm volatile("cp.async.commit_group;" ::: "memory");
            asm volatile("cp.async.wait_group 1;" ::: "memory");
        } else {
            asm volatile("cp.async.wait_group 0;" ::: "memory");
        }
        __syncthreads();

        const float* Ab = AsBuf + (i & 1) * TS;
        const float* Bb = BsBuf + (i & 1) * TS;

        #pragma unroll
        for (int ks = 0; ks < 4; ks++) {
            const int kk = ks * 8;
            uint32_t a[4][4], b[8][2];
            #pragma unroll
            for (int mt = 0; mt < 4; mt++) {
                const int rb = wm * 64 + mt * 16 + g;
                a[mt][0] = __float_as_uint(Ab[rb * 36 + kk + t]);
                a[mt][1] = __float_as_uint(Ab[(rb + 8) * 36 + kk + t]);
                a[mt][2] = __float_as_uint(Ab[rb * 36 + kk + t + 4]);
                a[mt][3] = __float_as_uint(Ab[(rb + 8) * 36 + kk + t + 4]);
            }
            #pragma unroll
            for (int nt = 0; nt < 8; nt++) {
                const int cb = wn * 64 + nt * 8 + g;
                b[nt][0] = __float_as_uint(Bb[cb * 36 + kk + t]);
                b[nt][1] = __float_as_uint(Bb[cb * 36 + kk + t + 4]);
            }
            #pragma unroll
            for (int mt = 0; mt < 4; mt++)
                #pragma unroll
                for (int nt = 0; nt < 8; nt++)
                    mma_tf32(acc[mt][nt], a[mt], b[nt]);
        }
        __syncthreads();
    }

    // ---- epilogue
    #pragma unroll
    for (int mt = 0; mt < 4; mt++) {
        #pragma unroll
        for (int nt = 0; nt < 8; nt++) {
            #pragma unroll
            for (int e = 0; e < 4; e++) {
                const int r = mBase + wm * 64 + mt * 16 + g + (e >> 1) * 8;
                const int c = nBase + wn * 64 + nt * 8 + t * 2 + (e & 1);
                const float val = acc[mt][nt][e] + bias[c];
                if (MODE == 0) {
                    Cout[(size_t)r * N + c] = val;
                } else if (MODE == 1) {
                    const int b_ = r >> 11, tt = r & 2047;
                    const int cc = c & 2047;
                    const int h = cc >> 7, d = cc & 127;
                    float* dst = (c < 2048) ? g_k : g_v;
                    dst[(((size_t)(b_ * NH + h)) * SEQT + tt) * HD + d] = val;
                } else {
                    const int b_ = r >> 11, tt = r & 2047;
                    const int h = c >> 7, d = c & 127;
                    g_q[(((size_t)(b_ * NH + h)) * SEQT + tt) * HD + d] = val;
                }
            }
        }
    }
}

// ============================================================================
// Flash attention (causal), tf32 mma — round-6 version (known good),
// except the epilogue store is tf32-rounded (g_att feeds the cp.async GEMM).
// ============================================================================
__global__ void __launch_bounds__(256, 1) attn_kernel()
{
    extern __shared__ float sm[];
    float* Qs = sm;                    // [128][132]
    float* Ks = Qs + 128 * 132;        // [64][132]
    float* Vs = Ks + 64 * 132;         // [64][132]
    float* Ps = Vs + 64 * 132;         // [128][68]

    const int bh = blockIdx.y;
    const int qt = blockIdx.x;
    const int qBase = qt * 128;
    const int tid = threadIdx.x, warp = tid >> 5, lane = tid & 31;
    const int g = lane >> 2, t = lane & 3;
    const int rowW = warp * 16;
    const float scale = 0.08838834764831845f;  // 1/sqrt(128)

    const float* Qg = g_q + (size_t)bh * SEQT * HD;
    const float* Kg = g_k + (size_t)bh * SEQT * HD;
    const float* Vg = g_v + (size_t)bh * SEQT * HD;

    #pragma unroll
    for (int i = 0; i < 16; i++) {
        int f = tid + i * 256;
        int r = f >> 5, c4 = (f & 31) << 2;
        float4 v = *(const float4*)(Qg + (size_t)(qBase + r) * HD + c4);
        Qs[r * 132 + c4 + 0] = tf32r(v.x * scale);
        Qs[r * 132 + c4 + 1] = tf32r(v.y * scale);
        Qs[r * 132 + c4 + 2] = tf32r(v.z * scale);
        Qs[r * 132 + c4 + 3] = tf32r(v.w * scale);
    }

    float o[16][4] = {};
    float m_[2], l_[2];
    m_[0] = m_[1] = -1e30f;
    l_[0] = l_[1] = 0.0f;

    const int nkt = 2 * qt + 2;
    for (int kt = 0; kt < nkt; kt++) {
        const int kBase = kt * 64;
        #pragma unroll
        for (int i = 0; i < 8; i++) {
            int f = tid + i * 256;
            int r = f >> 5, c4 = (f & 31) << 2;
            float4 kv = *(const float4*)(Kg + (size_t)(kBase + r) * HD + c4);
            Ks[r * 132 + c4 + 0] = tf32r(kv.x); Ks[r * 132 + c4 + 1] = tf32r(kv.y);
            Ks[r * 132 + c4 + 2] = tf32r(kv.z); Ks[r * 132 + c4 + 3] = tf32r(kv.w);
            float4 vv = *(const float4*)(Vg + (size_t)(kBase + r) * HD + c4);
            Vs[r * 132 + c4 + 0] = tf32r(vv.x); Vs[r * 132 + c4 + 1] = tf32r(vv.y);
            Vs[r * 132 + c4 + 2] = tf32r(vv.z); Vs[r * 132 + c4 + 3] = tf32r(vv.w);
        }
        __syncthreads();

        float s[8][4] = {};
        #pragma unroll
        for (int ks = 0; ks < 16; ks++) {
            const int kk = ks * 8;
            uint32_t a[4];
            a[0] = __float_as_uint(Qs[(rowW + g) * 132 + kk + t]);
            a[1] = __float_as_uint(Qs[(rowW + g + 8) * 132 + kk + t]);
            a[2] = __float_as_uint(Qs[(rowW + g) * 132 + kk + t + 4]);
            a[3] = __float_as_uint(Qs[(rowW + g + 8) * 132 + kk + t + 4]);
            #pragma unroll
            for (int nt = 0; nt < 8; nt++) {
                uint32_t b[2];
                b[0] = __float_as_uint(Ks[(nt * 8 + g) * 132 + kk + t]);
                b[1] = __float_as_uint(Ks[(nt * 8 + g) * 132 + kk + t + 4]);
                mma_tf32(s[nt], a, b);
            }
        }

        if (kt >= 2 * qt) {
            #pragma unroll
            for (int nt = 0; nt < 8; nt++)
                #pragma unroll
                for (int e = 0; e < 4; e++) {
                    const int key = kBase + nt * 8 + t * 2 + (e & 1);
                    const int qr = qBase + rowW + g + (e >> 1) * 8;
                    if (key > qr) s[nt][e] = -1e30f;
                }
        }

        float mnew[2];
        #pragma unroll
        for (int rr = 0; rr < 2; rr++) {
            float mx = -1e30f;
            #pragma unroll
            for (int nt = 0; nt < 8; nt++)
                mx = fmaxf(mx, fmaxf(s[nt][rr * 2], s[nt][rr * 2 + 1]));
            mx = fmaxf(mx, __shfl_xor_sync(0xffffffffu, mx, 1));
            mx = fmaxf(mx, __shfl_xor_sync(0xffffffffu, mx, 2));
            mnew[rr] = fmaxf(m_[rr], mx);
        }
        float corr[2];
        corr[0] = __expf(m_[0] - mnew[0]);
        corr[1] = __expf(m_[1] - mnew[1]);

        float rs[2] = {0.0f, 0.0f};
        #pragma unroll
        for (int nt = 0; nt < 8; nt++)
            #pragma unroll
            for (int e = 0; e < 4; e++) {
                const int rr = e >> 1;
                float p = __expf(s[nt][e] - mnew[rr]);
                s[nt][e] = p;
                rs[rr] += p;
            }
        #pragma unroll
        for (int rr = 0; rr < 2; rr++) {
            float v = rs[rr];
            v += __shfl_xor_sync(0xffffffffu, v, 1);
            v += __shfl_xor_sync(0xffffffffu, v, 2);
            l_[rr] = l_[rr] * corr[rr] + v;
            m_[rr] = mnew[rr];
        }

        #pragma unroll
        for (int nt = 0; nt < 16; nt++)
            #pragma unroll
            for (int e = 0; e < 4; e++)
                o[nt][e] *= corr[e >> 1];

        #pragma unroll
        for (int nt = 0; nt < 8; nt++) {
            const int c = nt * 8 + t * 2;
            Ps[(rowW + g) * 68 + c]     = tf32r(s[nt][0]);
            Ps[(rowW + g) * 68 + c + 1] = tf32r(s[nt][1]);
            Ps[(rowW + g + 8) * 68 + c]     = tf32r(s[nt][2]);
            Ps[(rowW + g + 8) * 68 + c + 1] = tf32r(s[nt][3]);
        }
        __syncwarp();

        #pragma unroll
        for (int ks = 0; ks < 8; ks++) {
            const int kk = ks * 8;
            uint32_t a[4];
            a[0] = __float_as_uint(Ps[(rowW + g) * 68 + kk + t]);
            a[1] = __float_as_uint(Ps[(rowW + g + 8) * 68 + kk + t]);
            a[2] = __float_as_uint(Ps[(rowW + g) * 68 + kk + t + 4]);
            a[3] = __float_as_uint(Ps[(rowW + g + 8) * 68 + kk + t + 4]);
            #pragma unroll
            for (int nt = 0; nt < 16; nt++) {
                uint32_t b[2];
                b[0] = __float_as_uint(Vs[(kk + t) * 132 + nt * 8 + g]);
                b[1] = __float_as_uint(Vs[(kk + t + 4) * 132 + nt * 8 + g]);
                mma_tf32(o[nt], a, b);
            }
        }
        __syncthreads();
    }

    // Write tf32-rounded output (g_att is the A operand of the cp.async out-GEMM)
    const int b_ = bh >> 4, h = bh & 15;
    const float inv0 = 1.0f / l_[0], inv1 = 1.0f / l_[1];
    #pragma unroll
    for (int nt = 0; nt < 16; nt++)
        #pragma unroll
        for (int e = 0; e < 4; e++) {
            const int rr = e >> 1;
            const int row = qBase + rowW + g + rr * 8;
            const int d = nt * 8 + t * 2 + (e & 1);
            g_att[((size_t)b_ * SEQT + row) * DIMC + h * HD + d] =
                tf32r(o[nt][e] * (rr ? inv1 : inv0));
        }
}

extern "C" void kernel_launch(void* const* d_in, const int* in_sizes, int n_in,
                              void* d_out, int out_size)
{
    const float* enc = (const float*)d_in[0];
    const float* dec = (const float*)d_in[1];
    const float* Wkv = (const float*)d_in[2];
    const float* bkv = (const float*)d_in[3];
    const float* Wq  = (const float*)d_in[4];
    const float* bq  = (const float*)d_in[5];
    const float* Wo  = (const float*)d_in[6];
    const float* bo  = (const float*)d_in[7];
    float* out = (float*)d_out;

    void *attPtr = nullptr, *wtPtr = nullptr, *encrPtr = nullptr, *decrPtr = nullptr;
    cudaGetSymbolAddress(&attPtr, g_att);
    cudaGetSymbolAddress(&wtPtr, g_wt);
    cudaGetSymbolAddress(&encrPtr, g_encr);
    cudaGetSymbolAddress(&decrPtr, g_decr);
    float* wtKV = (float*)wtPtr;                      // 4096 x 2048
    float* wtQ  = wtKV + (size_t)2 * DIMC * DIMC;     // 2048 x 2048
    float* wtO  = wtQ + (size_t)DIMC * DIMC;          // 2048 x 2048

    const int M = BATCH * SEQT;  // 8192
    dim3 blk128(128);
    dim3 tblk(32, 8);

    // 0a) tf32-round input copies (cp.async path needs pre-rounded A operands)
    const int RC_BLOCKS = (int)(((size_t)M * DIMC / 4) / 256);
    round_copy<<<RC_BLOCKS, 256>>>(enc, (float*)encrPtr);
    round_copy<<<RC_BLOCKS, 256>>>(dec, (float*)decrPtr);
    // 0b) Pre-transpose + tf32-round weights
    transpose_round<<<dim3(2 * DIMC / 32, DIMC / 32), tblk>>>(Wkv, wtKV, DIMC, 2 * DIMC);
    transpose_round<<<dim3(DIMC / 32, DIMC / 32), tblk>>>(Wq, wtQ, DIMC, DIMC);
    transpose_round<<<dim3(DIMC / 32, DIMC / 32), tblk>>>(Wo, wtO, DIMC, DIMC);

    const int GEMM_SMEM = 4 * TS * sizeof(float);  // 73728 B
    cudaFuncSetAttribute((const void*)gemm_ca<0>,
                         cudaFuncAttributeMaxDynamicSharedMemorySize, GEMM_SMEM);
    cudaFuncSetAttribute((const void*)gemm_ca<1>,
                         cudaFuncAttributeMaxDynamicSharedMemorySize, GEMM_SMEM);
    cudaFuncSetAttribute((const void*)gemm_ca<2>,
                         cudaFuncAttributeMaxDynamicSharedMemorySize, GEMM_SMEM);

    // 1) KV projection -> g_k, g_v (head-major)
    gemm_ca<1><<<dim3((2 * DIMC) / 128, M / 128), blk128, GEMM_SMEM>>>(
        (const float*)encrPtr, wtKV, bkv, nullptr, M, 2 * DIMC, DIMC);
    // 2) Q projection -> g_q (head-major)
    gemm_ca<2><<<dim3(DIMC / 128, M / 128), blk128, GEMM_SMEM>>>(
        (const float*)decrPtr, wtQ, bq, nullptr, M, DIMC, DIMC);

    // 3) Causal flash attention -> g_att (tf32-rounded)
    const size_t ATT_SMEM = (size_t)(128 * 132 + 64 * 132 + 64 * 132 + 128 * 68) * sizeof(float);
    cudaFuncSetAttribute((const void*)attn_kernel,
                         cudaFuncAttributeMaxDynamicSharedMemorySize, (int)ATT_SMEM);
    attn_kernel<<<dim3(SEQT / 128, BATCH * NH), dim3(256), ATT_SMEM>>>();

    // 4) Output projection -> d_out
    gemm_ca<0><<<dim3(DIMC / 128, M / 128), blk128, GEMM_SMEM>>>(
        (const float*)attPtr, wtO, bo, out, M, DIMC, DIMC);
}

// round 17
// speedup vs baseline: 1.7259x; 1.3757x over previous
#include <cuda_runtime.h>
#include <cstdint>

#define DIMC 2048
#define NH 16
#define HD 128
#define BATCH 4
#define SEQT 2048

// Scratch (device globals: allocation-free scratch per harness rules)
__device__ float g_k[(size_t)BATCH * NH * SEQT * HD];
__device__ float g_v[(size_t)BATCH * NH * SEQT * HD];
__device__ float g_q[(size_t)BATCH * NH * SEQT * HD];
__device__ float g_att[(size_t)BATCH * SEQT * DIMC];
// tf32-rounded copies: inputs and weights (cp.async path needs pre-rounded gmem)
__device__ float g_encr[(size_t)BATCH * SEQT * DIMC];
__device__ float g_decr[(size_t)BATCH * SEQT * DIMC];
__device__ float g_wr[(size_t)4 * DIMC * DIMC];   // Wkv (2048x4096) | Wq | Wo

__device__ __forceinline__ float tf32r(float x) {
    uint32_t u;
    asm("cvt.rna.tf32.f32 %0, %1;" : "=r"(u) : "f"(x));
    return __uint_as_float(u);
}

__device__ __forceinline__ uint32_t smem_u32(const void* p) {
    uint32_t a;
    asm("{ .reg .u64 t; cvta.to.shared.u64 t, %1; cvt.u32.u64 %0, t; }" : "=r"(a) : "l"(p));
    return a;
}

#define CP16(dst, src) \
    asm volatile("cp.async.ca.shared.global [%0], [%1], 16;" :: "r"(dst), "l"(src) : "memory")

__device__ __forceinline__ void mma_tf32(float* c, const uint32_t* a, const uint32_t* b) {
    asm volatile(
        "mma.sync.aligned.m16n8k8.row.col.f32.tf32.tf32.f32 "
        "{%0,%1,%2,%3}, {%4,%5,%6,%7}, {%8,%9}, {%0,%1,%2,%3};"
        : "+f"(c[0]), "+f"(c[1]), "+f"(c[2]), "+f"(c[3])
        : "r"(a[0]), "r"(a[1]), "r"(a[2]), "r"(a[3]), "r"(b[0]), "r"(b[1]));
}

// ============================================================================
// tf32-round copy: dst[i] = tf32(src[i]) (float4 per thread)
// ============================================================================
__global__ void round_copy(const float* __restrict__ src, float* __restrict__ dst) {
    const size_t i = ((size_t)blockIdx.x * blockDim.x + threadIdx.x) * 4;
    float4 v = *(const float4*)(src + i);
    v.x = tf32r(v.x); v.y = tf32r(v.y); v.z = tf32r(v.z); v.w = tf32r(v.w);
    *(float4*)(dst + i) = v;
}

// ============================================================================
// tf32 GEMM, cp.async double-buffered, R6 compute structure.
// C[M,N] = A[M,K] @ W[K,N] + bias. A and W pre-rounded to tf32 in gmem.
// BM=128, BN=128, BK=32; 256 threads, 8 warps (4 along M x 2 along N),
// warp tile 32x64, acc 64 regs/thread, occ 2.
// Stage layout: As[128][36] then Bs[32][132]; 8832 floats/stage, 2 stages.
// MODE 0: plain write, MODE 1: KV scatter, MODE 2: Q scatter.
// ============================================================================
#define STG 8832  // floats per stage (4608 A + 4224 B)

template <int MODE>
__global__ void __launch_bounds__(256, 2) gemm_db(
    const float* __restrict__ A, const float* __restrict__ W,
    const float* __restrict__ bias, float* __restrict__ Cout,
    int M, int N, int K)
{
    extern __shared__ float sm[];
    const int tid = threadIdx.x, warp = tid >> 5, lane = tid & 31;
    const int g = lane >> 2, t = lane & 3;
    const int wm = warp >> 1, wn = warp & 1;
    const int mBase = blockIdx.y * 128, nBase = blockIdx.x * 128;
    const uint32_t sbase = smem_u32(sm);

    // Per-thread cp.async coordinates (fixed across tiles)
    const int am = tid >> 3, aj = tid & 7;        // A: 4 rows per thread step 32
    const int br = tid >> 5, bc = tid & 31;       // B: 4 rows per thread step 8

    float acc[2][8][4] = {};
    const int KIT = K >> 5;

    // ---- prologue: issue tile 0 into stage 0
    {
        const uint32_t dA = sbase;
        const uint32_t dB = sbase + 4608u * 4u;
        #pragma unroll
        for (int u = 0; u < 4; u++) {
            const int m = am + u * 32;
            CP16(dA + (uint32_t)(m * 36 + aj * 4) * 4,
                 A + (size_t)(mBase + m) * K + 4 * aj);
        }
        #pragma unroll
        for (int u = 0; u < 4; u++) {
            const int r = br + u * 8;
            CP16(dB + (uint32_t)(r * 132 + bc * 4) * 4,
                 W + (size_t)r * N + nBase + 4 * bc);
        }
        asm volatile("cp.async.commit_group;" ::: "memory");
    }

    for (int i = 0; i < KIT; i++) {
        if (i + 1 < KIT) {
            const int k0 = (i + 1) << 5;
            const uint32_t dA = sbase + (uint32_t)(((i + 1) & 1) * STG) * 4u;
            const uint32_t dB = dA + 4608u * 4u;
            #pragma unroll
            for (int u = 0; u < 4; u++) {
                const int m = am + u * 32;
                CP16(dA + (uint32_t)(m * 36 + aj * 4) * 4,
                     A + (size_t)(mBase + m) * K + k0 + 4 * aj);
            }
            #pragma unroll
            for (int u = 0; u < 4; u++) {
                const int r = br + u * 8;
                CP16(dB + (uint32_t)(r * 132 + bc * 4) * 4,
                     W + (size_t)(k0 + r) * N + nBase + 4 * bc);
            }
            asm volatile("cp.async.commit_group;" ::: "memory");
            asm volatile("cp.async.wait_group 1;" ::: "memory");
        } else {
            asm volatile("cp.async.wait_group 0;" ::: "memory");
        }
        __syncthreads();

        const float* As = sm + (i & 1) * STG;      // [128][36]
        const float* Bs = As + 4608;               // [32][132]

        #pragma unroll
        for (int ks = 0; ks < 4; ks++) {
            const int kk = ks * 8;
            uint32_t a[2][4], b[8][2];
            #pragma unroll
            for (int mt = 0; mt < 2; mt++) {
                const int rb = wm * 32 + mt * 16;
                a[mt][0] = __float_as_uint(As[(rb + g) * 36 + kk + t]);
                a[mt][1] = __float_as_uint(As[(rb + g + 8) * 36 + kk + t]);
                a[mt][2] = __float_as_uint(As[(rb + g) * 36 + kk + t + 4]);
                a[mt][3] = __float_as_uint(As[(rb + g + 8) * 36 + kk + t + 4]);
            }
            #pragma unroll
            for (int nt = 0; nt < 8; nt++) {
                const int cb = wn * 64 + nt * 8;
                b[nt][0] = __float_as_uint(Bs[(kk + t) * 132 + cb + g]);
                b[nt][1] = __float_as_uint(Bs[(kk + t + 4) * 132 + cb + g]);
            }
            #pragma unroll
            for (int mt = 0; mt < 2; mt++)
                #pragma unroll
                for (int nt = 0; nt < 8; nt++)
                    mma_tf32(acc[mt][nt], a[mt], b[nt]);
        }
        __syncthreads();
    }

    // ---- epilogue (R6)
    #pragma unroll
    for (int mt = 0; mt < 2; mt++) {
        #pragma unroll
        for (int nt = 0; nt < 8; nt++) {
            #pragma unroll
            for (int e = 0; e < 4; e++) {
                const int r = mBase + wm * 32 + mt * 16 + g + (e >> 1) * 8;
                const int c = nBase + wn * 64 + nt * 8 + t * 2 + (e & 1);
                const float val = acc[mt][nt][e] + bias[c];
                if (MODE == 0) {
                    Cout[(size_t)r * N + c] = val;
                } else if (MODE == 1) {
                    const int b_ = r >> 11, tt = r & 2047;
                    const int cc = c & 2047;
                    const int h = cc >> 7, d = cc & 127;
                    float* dst = (c < 2048) ? g_k : g_v;
                    dst[(((size_t)(b_ * NH + h)) * SEQT + tt) * HD + d] = val;
                } else {
                    const int b_ = r >> 11, tt = r & 2047;
                    const int h = c >> 7, d = c & 127;
                    g_q[(((size_t)(b_ * NH + h)) * SEQT + tt) * HD + d] = val;
                }
            }
        }
    }
}

// ============================================================================
// Flash attention (causal), tf32 mma — round-6 version (known good).
// Epilogue writes g_att tf32-rounded (it is the A operand of the out GEMM).
// ============================================================================
__global__ void __launch_bounds__(256, 1) attn_kernel()
{
    extern __shared__ float sm[];
    float* Qs = sm;                    // [128][132]
    float* Ks = Qs + 128 * 132;        // [64][132]
    float* Vs = Ks + 64 * 132;         // [64][132]
    float* Ps = Vs + 64 * 132;         // [128][68]

    const int bh = blockIdx.y;
    const int qt = blockIdx.x;
    const int qBase = qt * 128;
    const int tid = threadIdx.x, warp = tid >> 5, lane = tid & 31;
    const int g = lane >> 2, t = lane & 3;
    const int rowW = warp * 16;
    const float scale = 0.08838834764831845f;  // 1/sqrt(128)

    const float* Qg = g_q + (size_t)bh * SEQT * HD;
    const float* Kg = g_k + (size_t)bh * SEQT * HD;
    const float* Vg = g_v + (size_t)bh * SEQT * HD;

    #pragma unroll
    for (int i = 0; i < 16; i++) {
        int f = tid + i * 256;
        int r = f >> 5, c4 = (f & 31) << 2;
        float4 v = *(const float4*)(Qg + (size_t)(qBase + r) * HD + c4);
        Qs[r * 132 + c4 + 0] = tf32r(v.x * scale);
        Qs[r * 132 + c4 + 1] = tf32r(v.y * scale);
        Qs[r * 132 + c4 + 2] = tf32r(v.z * scale);
        Qs[r * 132 + c4 + 3] = tf32r(v.w * scale);
    }

    float o[16][4] = {};
    float m_[2], l_[2];
    m_[0] = m_[1] = -1e30f;
    l_[0] = l_[1] = 0.0f;

    const int nkt = 2 * qt + 2;
    for (int kt = 0; kt < nkt; kt++) {
        const int kBase = kt * 64;
        #pragma unroll
        for (int i = 0; i < 8; i++) {
            int f = tid + i * 256;
            int r = f >> 5, c4 = (f & 31) << 2;
            float4 kv = *(const float4*)(Kg + (size_t)(kBase + r) * HD + c4);
            Ks[r * 132 + c4 + 0] = tf32r(kv.x); Ks[r * 132 + c4 + 1] = tf32r(kv.y);
            Ks[r * 132 + c4 + 2] = tf32r(kv.z); Ks[r * 132 + c4 + 3] = tf32r(kv.w);
            float4 vv = *(const float4*)(Vg + (size_t)(kBase + r) * HD + c4);
            Vs[r * 132 + c4 + 0] = tf32r(vv.x); Vs[r * 132 + c4 + 1] = tf32r(vv.y);
            Vs[r * 132 + c4 + 2] = tf32r(vv.z); Vs[r * 132 + c4 + 3] = tf32r(vv.w);
        }
        __syncthreads();

        float s[8][4] = {};
        #pragma unroll
        for (int ks = 0; ks < 16; ks++) {
            const int kk = ks * 8;
            uint32_t a[4];
            a[0] = __float_as_uint(Qs[(rowW + g) * 132 + kk + t]);
            a[1] = __float_as_uint(Qs[(rowW + g + 8) * 132 + kk + t]);
            a[2] = __float_as_uint(Qs[(rowW + g) * 132 + kk + t + 4]);
            a[3] = __float_as_uint(Qs[(rowW + g + 8) * 132 + kk + t + 4]);
            #pragma unroll
            for (int nt = 0; nt < 8; nt++) {
                uint32_t b[2];
                b[0] = __float_as_uint(Ks[(nt * 8 + g) * 132 + kk + t]);
                b[1] = __float_as_uint(Ks[(nt * 8 + g) * 132 + kk + t + 4]);
                mma_tf32(s[nt], a, b);
            }
        }

        if (kt >= 2 * qt) {
            #pragma unroll
            for (int nt = 0; nt < 8; nt++)
                #pragma unroll
                for (int e = 0; e < 4; e++) {
                    const int key = kBase + nt * 8 + t * 2 + (e & 1);
                    const int qr = qBase + rowW + g + (e >> 1) * 8;
                    if (key > qr) s[nt][e] = -1e30f;
                }
        }

        float mnew[2];
        #pragma unroll
        for (int rr = 0; rr < 2; rr++) {
            float mx = -1e30f;
            #pragma unroll
            for (int nt = 0; nt < 8; nt++)
                mx = fmaxf(mx, fmaxf(s[nt][rr * 2], s[nt][rr * 2 + 1]));
            mx = fmaxf(mx, __shfl_xor_sync(0xffffffffu, mx, 1));
            mx = fmaxf(mx, __shfl_xor_sync(0xffffffffu, mx, 2));
            mnew[rr] = fmaxf(m_[rr], mx);
        }
        float corr[2];
        corr[0] = __expf(m_[0] - mnew[0]);
        corr[1] = __expf(m_[1] - mnew[1]);

        float rs[2] = {0.0f, 0.0f};
        #pragma unroll
        for (int nt = 0; nt < 8; nt++)
            #pragma unroll
            for (int e = 0; e < 4; e++) {
                const int rr = e >> 1;
                float p = __expf(s[nt][e] - mnew[rr]);
                s[nt][e] = p;
                rs[rr] += p;
            }
        #pragma unroll
        for (int rr = 0; rr < 2; rr++) {
            float v = rs[rr];
            v += __shfl_xor_sync(0xffffffffu, v, 1);
            v += __shfl_xor_sync(0xffffffffu, v, 2);
            l_[rr] = l_[rr] * corr[rr] + v;
            m_[rr] = mnew[rr];
        }

        #pragma unroll
        for (int nt = 0; nt < 16; nt++)
            #pragma unroll
            for (int e = 0; e < 4; e++)
                o[nt][e] *= corr[e >> 1];

        #pragma unroll
        for (int nt = 0; nt < 8; nt++) {
            const int c = nt * 8 + t * 2;
            Ps[(rowW + g) * 68 + c]     = tf32r(s[nt][0]);
            Ps[(rowW + g) * 68 + c + 1] = tf32r(s[nt][1]);
            Ps[(rowW + g + 8) * 68 + c]     = tf32r(s[nt][2]);
            Ps[(rowW + g + 8) * 68 + c + 1] = tf32r(s[nt][3]);
        }
        __syncwarp();

        #pragma unroll
        for (int ks = 0; ks < 8; ks++) {
            const int kk = ks * 8;
            uint32_t a[4];
            a[0] = __float_as_uint(Ps[(rowW + g) * 68 + kk + t]);
            a[1] = __float_as_uint(Ps[(rowW + g + 8) * 68 + kk + t]);
            a[2] = __float_as_uint(Ps[(rowW + g) * 68 + kk + t + 4]);
            a[3] = __float_as_uint(Ps[(rowW + g + 8) * 68 + kk + t + 4]);
            #pragma unroll
            for (int nt = 0; nt < 16; nt++) {
                uint32_t b[2];
                b[0] = __float_as_uint(Vs[(kk + t) * 132 + nt * 8 + g]);
                b[1] = __float_as_uint(Vs[(kk + t + 4) * 132 + nt * 8 + g]);
                mma_tf32(o[nt], a, b);
            }
        }
        __syncthreads();
    }

    const int b_ = bh >> 4, h = bh & 15;
    const float inv0 = 1.0f / l_[0], inv1 = 1.0f / l_[1];
    #pragma unroll
    for (int nt = 0; nt < 16; nt++)
        #pragma unroll
        for (int e = 0; e < 4; e++) {
            const int rr = e >> 1;
            const int row = qBase + rowW + g + rr * 8;
            const int d = nt * 8 + t * 2 + (e & 1);
            g_att[((size_t)b_ * SEQT + row) * DIMC + h * HD + d] =
                tf32r(o[nt][e] * (rr ? inv1 : inv0));
        }
}

extern "C" void kernel_launch(void* const* d_in, const int* in_sizes, int n_in,
                              void* d_out, int out_size)
{
    const float* enc = (const float*)d_in[0];
    const float* dec = (const float*)d_in[1];
    const float* Wkv = (const float*)d_in[2];
    const float* bkv = (const float*)d_in[3];
    const float* Wq  = (const float*)d_in[4];
    const float* bq  = (const float*)d_in[5];
    const float* Wo  = (const float*)d_in[6];
    const float* bo  = (const float*)d_in[7];
    float* out = (float*)d_out;

    void *attPtr = nullptr, *wrPtr = nullptr, *encrPtr = nullptr, *decrPtr = nullptr;
    cudaGetSymbolAddress(&attPtr, g_att);
    cudaGetSymbolAddress(&wrPtr, g_wr);
    cudaGetSymbolAddress(&encrPtr, g_encr);
    cudaGetSymbolAddress(&decrPtr, g_decr);
    float* rWkv = (float*)wrPtr;                      // 2048 x 4096
    float* rWq  = rWkv + (size_t)2 * DIMC * DIMC;     // 2048 x 2048
    float* rWo  = rWq + (size_t)DIMC * DIMC;          // 2048 x 2048

    const int M = BATCH * SEQT;  // 8192

    // 0) tf32-round inputs and weights (flat copies, no transpose)
    round_copy<<<(int)(((size_t)M * DIMC / 4) / 256), 256>>>(enc, (float*)encrPtr);
    round_copy<<<(int)(((size_t)M * DIMC / 4) / 256), 256>>>(dec, (float*)decrPtr);
    round_copy<<<(int)(((size_t)2 * DIMC * DIMC / 4) / 256), 256>>>(Wkv, rWkv);
    round_copy<<<(int)(((size_t)DIMC * DIMC / 4) / 256), 256>>>(Wq, rWq);
    round_copy<<<(int)(((size_t)DIMC * DIMC / 4) / 256), 256>>>(Wo, rWo);

    const int GEMM_SMEM = 2 * STG * sizeof(float);  // 70656 B
    cudaFuncSetAttribute((const void*)gemm_db<0>,
                         cudaFuncAttributeMaxDynamicSharedMemorySize, GEMM_SMEM);
    cudaFuncSetAttribute((const void*)gemm_db<1>,
                         cudaFuncAttributeMaxDynamicSharedMemorySize, GEMM_SMEM);
    cudaFuncSetAttribute((const void*)gemm_db<2>,
                         cudaFuncAttributeMaxDynamicSharedMemorySize, GEMM_SMEM);

    dim3 blk(256);
    // 1) KV projection -> g_k, g_v (head-major)
    gemm_db<1><<<dim3((2 * DIMC) / 128, M / 128), blk, GEMM_SMEM>>>(
        (const float*)encrPtr, rWkv, bkv, nullptr, M, 2 * DIMC, DIMC);
    // 2) Q projection -> g_q (head-major)
    gemm_db<2><<<dim3(DIMC / 128, M / 128), blk, GEMM_SMEM>>>(
        (const float*)decrPtr, rWq, bq, nullptr, M, DIMC, DIMC);

    // 3) Causal flash attention -> g_att (tf32-rounded)
    const size_t ATT_SMEM = (size_t)(128 * 132 + 64 * 132 + 64 * 132 + 128 * 68) * sizeof(float);
    cudaFuncSetAttribute((const void*)attn_kernel,
                         cudaFuncAttributeMaxDynamicSharedMemorySize, (int)ATT_SMEM);
    attn_kernel<<<dim3(SEQT / 128, BATCH * NH), dim3(256), ATT_SMEM>>>();

    // 4) Output projection -> d_out
    gemm_db<0><<<dim3(DIMC / 128, M / 128), blk, GEMM_SMEM>>>(
        (const float*)attPtr, rWo, bo, out, M, DIMC, DIMC);
}